// round 3
// baseline (speedup 1.0000x reference)
#include <cuda_runtime.h>
#include <cuda_fp16.h>
#include <cstdint>
#include <cstddef>

// ---------------- problem constants ----------------
#define TOKENS 8192
#define KDIM   4096
#define ODIM   4096

#define BM 128
#define BN 128
#define BK 32
#define KT (KDIM / BK)      // 128 k-iterations
#define STAGES 4
#define NTHREADS 256

// per-stage smem: A 128x32 fp16 = 8192 B, B 128x32 fp16 = 8192 B
#define A_STAGE_BYTES (BM * BK * 2)
#define B_STAGE_BYTES (BN * BK * 2)
#define STAGE_BYTES   (A_STAGE_BYTES + B_STAGE_BYTES)   // 16384
#define SMEM_TOTAL    (STAGES * STAGE_BYTES)            // 65536

// ---------------- scratch (no runtime allocation allowed) ----------------
__device__ __half g_xh[(size_t)TOKENS * KDIM];   // 64 MB
__device__ __half g_wq[(size_t)ODIM * KDIM];     // 32 MB

// ---------------- helpers ----------------
__device__ __forceinline__ uint32_t smem_to_u32(const void* p) {
    uint32_t a;
    asm("{ .reg .u64 t; cvta.to.shared.u64 t, %1; cvt.u32.u64 %0, t; }" : "=r"(a) : "l"(p));
    return a;
}
__device__ __forceinline__ uint32_t sw128(uint32_t off) {
    return off ^ ((off >> 3) & 0x70);
}
__device__ __forceinline__ void cp_async16(uint32_t dst, const void* src) {
    asm volatile("cp.async.cg.shared.global [%0], [%1], 16;" :: "r"(dst), "l"(src));
}
__device__ __forceinline__ void cp_commit() {
    asm volatile("cp.async.commit_group;" ::: "memory");
}
template <int N>
__device__ __forceinline__ void cp_wait() {
    asm volatile("cp.async.wait_group %0;" :: "n"(N) : "memory");
}
__device__ __forceinline__ void ldsm4(uint32_t* r, uint32_t addr) {
    asm volatile("ldmatrix.sync.aligned.m8n8.x4.shared.b16 {%0,%1,%2,%3}, [%4];"
                 : "=r"(r[0]), "=r"(r[1]), "=r"(r[2]), "=r"(r[3]) : "r"(addr));
}
__device__ __forceinline__ void mma16816(float* c, const uint32_t* a,
                                         uint32_t b0, uint32_t b1) {
    asm volatile(
        "mma.sync.aligned.m16n8k16.row.col.f32.f16.f16.f32 "
        "{%0,%1,%2,%3}, {%4,%5,%6,%7}, {%8,%9}, {%0,%1,%2,%3};"
        : "+f"(c[0]), "+f"(c[1]), "+f"(c[2]), "+f"(c[3])
        : "r"(a[0]), "r"(a[1]), "r"(a[2]), "r"(a[3]), "r"(b0), "r"(b1));
}

// ---------------- prep kernels ----------------
// quantize weight -> fp16 levels {sorted(+-b0 +- b1)}, midpoint thresholds,
// searchsorted(side=left): idx = #{thres < w}
__global__ void quantize_w_kernel(const float* __restrict__ w,
                                  const float* __restrict__ basis, int n4) {
    float b0 = basis[0], b1 = basis[1];
    float v0 = -b0 - b1, v1 = -b0 + b1, v2 = b0 - b1, v3 = b0 + b1;
    float t;
    if (v0 > v1) { t = v0; v0 = v1; v1 = t; }
    if (v2 > v3) { t = v2; v2 = v3; v3 = t; }
    if (v0 > v2) { t = v0; v0 = v2; v2 = t; }
    if (v1 > v3) { t = v1; v1 = v3; v3 = t; }
    if (v1 > v2) { t = v1; v1 = v2; v2 = t; }
    float th0 = 0.5f * (v0 + v1), th1 = 0.5f * (v1 + v2), th2 = 0.5f * (v2 + v3);
    __half lev[4] = { __float2half_rn(v0), __float2half_rn(v1),
                      __float2half_rn(v2), __float2half_rn(v3) };
    int i = blockIdx.x * blockDim.x + threadIdx.x;
    if (i >= n4) return;
    float4 x = reinterpret_cast<const float4*>(w)[i];
    __half q0 = lev[(x.x > th0) + (x.x > th1) + (x.x > th2)];
    __half q1 = lev[(x.y > th0) + (x.y > th1) + (x.y > th2)];
    __half q2 = lev[(x.z > th0) + (x.z > th1) + (x.z > th2)];
    __half q3 = lev[(x.w > th0) + (x.w > th1) + (x.w > th2)];
    __half2 p0 = __halves2half2(q0, q1);
    __half2 p1 = __halves2half2(q2, q3);
    uint2 o;
    o.x = *reinterpret_cast<uint32_t*>(&p0);
    o.y = *reinterpret_cast<uint32_t*>(&p1);
    reinterpret_cast<uint2*>(g_wq)[i] = o;
}

__global__ void convert_x_kernel(const float* __restrict__ x, int n4) {
    int i = blockIdx.x * blockDim.x + threadIdx.x;
    if (i >= n4) return;
    float4 v = reinterpret_cast<const float4*>(x)[i];
    __half2 a = __floats2half2_rn(v.x, v.y);
    __half2 b = __floats2half2_rn(v.z, v.w);
    uint2 o;
    o.x = *reinterpret_cast<uint32_t*>(&a);
    o.y = *reinterpret_cast<uint32_t*>(&b);
    reinterpret_cast<uint2*>(g_xh)[i] = o;
}

// ---------------- GEMM mainloop ----------------
// load one k-chunk (BK=32) for stage s: A tile [BM][BK], B tile [BN][BK],
// each row = 64 B = 4 x 16 B chunks, SW128-swizzled byte offsets.
__device__ __forceinline__ void load_stage(uint32_t sb, int s, int kt, int tid,
                                           const __half* gA, const __half* gB) {
    uint32_t a_off = sb + s * STAGE_BYTES;
    uint32_t b_off = a_off + A_STAGE_BYTES;
#pragma unroll
    for (int p = 0; p < 2; p++) {                  // 512 16B-chunks / 256 thr
        int id = tid + p * NTHREADS;
        int row = id >> 2, ch = id & 3;
        uint32_t off = (uint32_t)row * 64 + (uint32_t)ch * 16;
        cp_async16(a_off + sw128(off),
                   gA + (size_t)row * KDIM + kt * BK + ch * 8);
    }
#pragma unroll
    for (int p = 0; p < 2; p++) {
        int id = tid + p * NTHREADS;
        int row = id >> 2, ch = id & 3;
        uint32_t off = (uint32_t)row * 64 + (uint32_t)ch * 16;
        cp_async16(b_off + sw128(off),
                   gB + (size_t)row * KDIM + kt * BK + ch * 8);
    }
    cp_commit();
}

__global__ void __launch_bounds__(NTHREADS, 2)
gemm_kernel(const float* __restrict__ bias, float* __restrict__ out) {
    extern __shared__ char smem[];
    uint32_t sb = smem_to_u32(smem);
    int tid = threadIdx.x;
    int wid = tid >> 5, lane = tid & 31;
    int warp_m = wid >> 2;            // 0..1  (64 rows each)
    int warp_n = wid & 3;             // 0..3  (32 cols each)
    int nbase = blockIdx.x * BN;
    int mbase = blockIdx.y * BM;

    const __half* gA = g_xh + (size_t)mbase * KDIM;
    const __half* gB = g_wq + (size_t)nbase * KDIM;

    float acc[4][4][4];
#pragma unroll
    for (int i = 0; i < 4; i++)
#pragma unroll
        for (int j = 0; j < 4; j++)
#pragma unroll
            for (int r = 0; r < 4; r++) acc[i][j][r] = 0.f;

    // ldmatrix per-lane base addressing (rows within tile, 16B chunk index)
    int a_row_base = warp_m * 64 + ((lane >> 3) & 1) * 8 + (lane & 7);
    int b_row_base = warp_n * 32 + ((lane >> 3) & 1) * 8 + (lane & 7);
    int ch_base = lane >> 4;          // 0..1

    // prologue
#pragma unroll
    for (int s = 0; s < STAGES - 1; s++) load_stage(sb, s, s, tid, gA, gB);

    for (int kt = 0; kt < KT; kt++) {
        cp_wait<STAGES - 2>();
        __syncthreads();

        int nxt = kt + STAGES - 1;
        if (nxt < KT) load_stage(sb, nxt & (STAGES - 1), nxt, tid, gA, gB);
        else cp_commit();

        int cur = kt & (STAGES - 1);
        uint32_t a_off = sb + cur * STAGE_BYTES;
        uint32_t b_off = a_off + A_STAGE_BYTES;

#pragma unroll
        for (int kk = 0; kk < 2; kk++) {
            uint32_t afr[4][4];
#pragma unroll
            for (int i = 0; i < 4; i++) {
                uint32_t off = (uint32_t)(a_row_base + i * 16) * 64
                             + (uint32_t)(ch_base + kk * 2) * 16;
                ldsm4(afr[i], a_off + sw128(off));
            }
            uint32_t bfr[2][4];
#pragma unroll
            for (int g = 0; g < 2; g++) {
                uint32_t off = (uint32_t)(b_row_base + g * 16) * 64
                             + (uint32_t)(ch_base + kk * 2) * 16;
                ldsm4(bfr[g], b_off + sw128(off));
            }
#pragma unroll
            for (int i = 0; i < 4; i++)
#pragma unroll
                for (int j = 0; j < 4; j++)
                    mma16816(acc[i][j], afr[i],
                             bfr[j >> 1][j & 1], bfr[j >> 1][(j & 1) + 2]);
        }
        __syncthreads();
    }

    // epilogue: direct to gmem with bias
    int m0 = mbase + warp_m * 64 + (lane >> 2);
    int n0 = nbase + warp_n * 32 + (lane & 3) * 2;
    float2 bj[4];
#pragma unroll
    for (int j = 0; j < 4; j++)
        bj[j] = *reinterpret_cast<const float2*>(bias + n0 + j * 8);
#pragma unroll
    for (int i = 0; i < 4; i++) {
        float* row_lo = out + (size_t)(m0 + i * 16) * ODIM;
        float* row_hi = out + (size_t)(m0 + i * 16 + 8) * ODIM;
#pragma unroll
        for (int j = 0; j < 4; j++) {
            float2 lo = { acc[i][j][0] + bj[j].x, acc[i][j][1] + bj[j].y };
            float2 hi = { acc[i][j][2] + bj[j].x, acc[i][j][3] + bj[j].y };
            *reinterpret_cast<float2*>(row_lo + n0 + j * 8) = lo;
            *reinterpret_cast<float2*>(row_hi + n0 + j * 8) = hi;
        }
    }
}

// ---------------- launch ----------------
extern "C" void kernel_launch(void* const* d_in, const int* in_sizes, int n_in,
                              void* d_out, int out_size) {
    const float* x     = (const float*)d_in[0];
    const float* w     = (const float*)d_in[1];
    const float* bias  = (const float*)d_in[2];
    const float* basis = (const float*)d_in[3];
    float* out = (float*)d_out;

    cudaFuncSetAttribute(gemm_kernel, cudaFuncAttributeMaxDynamicSharedMemorySize,
                         SMEM_TOTAL);

    int nw4 = (ODIM * KDIM) / 4;
    int nx4 = (TOKENS * KDIM) / 4;
    quantize_w_kernel<<<(nw4 + 255) / 256, 256>>>(w, basis, nw4);
    convert_x_kernel<<<(nx4 + 255) / 256, 256>>>(x, nx4);
    gemm_kernel<<<dim3(ODIM / BN, TOKENS / BM), NTHREADS, SMEM_TOTAL>>>(bias, out);
}

// round 4
// speedup vs baseline: 1.1781x; 1.1781x over previous
#include <cuda_runtime.h>
#include <cuda_fp16.h>
#include <cstdint>
#include <cstddef>

// ---------------- problem constants ----------------
#define TOKENS 8192
#define KDIM   4096
#define ODIM   4096

#define BM 128
#define BN 128
#define BK 64
#define KT (KDIM / BK)      // 64 k-iterations
#define STAGES 3
#define NTHREADS 256

// per-stage smem: A 128x64 fp16 = 16384 B, B 128x64 fp16 = 16384 B
#define A_STAGE_BYTES (BM * BK * 2)
#define B_STAGE_BYTES (BN * BK * 2)
#define STAGE_BYTES   (A_STAGE_BYTES + B_STAGE_BYTES)   // 32768
#define SMEM_TOTAL    (STAGES * STAGE_BYTES)            // 98304

// ---------------- scratch (no runtime allocation allowed) ----------------
__device__ __half g_xh[(size_t)TOKENS * KDIM];   // 64 MB
__device__ __half g_wq[(size_t)ODIM * KDIM];     // 32 MB

// ---------------- helpers ----------------
__device__ __forceinline__ uint32_t smem_to_u32(const void* p) {
    uint32_t a;
    asm("{ .reg .u64 t; cvta.to.shared.u64 t, %1; cvt.u32.u64 %0, t; }" : "=r"(a) : "l"(p));
    return a;
}
__device__ __forceinline__ uint32_t sw128(uint32_t off) {
    return off ^ ((off >> 3) & 0x70);
}
__device__ __forceinline__ void cp_async16(uint32_t dst, const void* src) {
    asm volatile("cp.async.cg.shared.global [%0], [%1], 16;" :: "r"(dst), "l"(src));
}
__device__ __forceinline__ void cp_commit() {
    asm volatile("cp.async.commit_group;" ::: "memory");
}
template <int N>
__device__ __forceinline__ void cp_wait() {
    asm volatile("cp.async.wait_group %0;" :: "n"(N) : "memory");
}
__device__ __forceinline__ void ldsm4(uint32_t* r, uint32_t addr) {
    asm volatile("ldmatrix.sync.aligned.m8n8.x4.shared.b16 {%0,%1,%2,%3}, [%4];"
                 : "=r"(r[0]), "=r"(r[1]), "=r"(r[2]), "=r"(r[3]) : "r"(addr));
}
__device__ __forceinline__ void mma16816(float* c, const uint32_t* a,
                                         uint32_t b0, uint32_t b1) {
    asm volatile(
        "mma.sync.aligned.m16n8k16.row.col.f32.f16.f16.f32 "
        "{%0,%1,%2,%3}, {%4,%5,%6,%7}, {%8,%9}, {%0,%1,%2,%3};"
        : "+f"(c[0]), "+f"(c[1]), "+f"(c[2]), "+f"(c[3])
        : "r"(a[0]), "r"(a[1]), "r"(a[2]), "r"(a[3]), "r"(b0), "r"(b1));
}

// ---------------- prep kernels ----------------
// quantize weight -> fp16 levels {sorted(+-b0 +- b1)}, midpoint thresholds,
// searchsorted(side=left): pick level i iff thres[i-1] < w <= thres[i].
// Branchless selp chain (no dynamically-indexed local array).
__global__ void quantize_w_kernel(const float* __restrict__ w,
                                  const float* __restrict__ basis, int n4) {
    float b0 = basis[0], b1 = basis[1];
    float v0 = -b0 - b1, v1 = -b0 + b1, v2 = b0 - b1, v3 = b0 + b1;
    float t;
    if (v0 > v1) { t = v0; v0 = v1; v1 = t; }
    if (v2 > v3) { t = v2; v2 = v3; v3 = t; }
    if (v0 > v2) { t = v0; v0 = v2; v2 = t; }
    if (v1 > v3) { t = v1; v1 = v3; v3 = t; }
    if (v1 > v2) { t = v1; v1 = v2; v2 = t; }
    float th0 = 0.5f * (v0 + v1), th1 = 0.5f * (v1 + v2), th2 = 0.5f * (v2 + v3);
    int i = blockIdx.x * blockDim.x + threadIdx.x;
    if (i >= n4) return;
    float4 x = reinterpret_cast<const float4*>(w)[i];
    float q0 = (x.x > th1) ? ((x.x > th2) ? v3 : v2) : ((x.x > th0) ? v1 : v0);
    float q1 = (x.y > th1) ? ((x.y > th2) ? v3 : v2) : ((x.y > th0) ? v1 : v0);
    float q2 = (x.z > th1) ? ((x.z > th2) ? v3 : v2) : ((x.z > th0) ? v1 : v0);
    float q3 = (x.w > th1) ? ((x.w > th2) ? v3 : v2) : ((x.w > th0) ? v1 : v0);
    __half2 p0 = __floats2half2_rn(q0, q1);
    __half2 p1 = __floats2half2_rn(q2, q3);
    uint2 o;
    o.x = *reinterpret_cast<uint32_t*>(&p0);
    o.y = *reinterpret_cast<uint32_t*>(&p1);
    reinterpret_cast<uint2*>(g_wq)[i] = o;
}

__global__ void convert_x_kernel(const float* __restrict__ x, int n4) {
    int i = blockIdx.x * blockDim.x + threadIdx.x;
    if (i >= n4) return;
    float4 v = reinterpret_cast<const float4*>(x)[i];
    __half2 a = __floats2half2_rn(v.x, v.y);
    __half2 b = __floats2half2_rn(v.z, v.w);
    uint2 o;
    o.x = *reinterpret_cast<uint32_t*>(&a);
    o.y = *reinterpret_cast<uint32_t*>(&b);
    reinterpret_cast<uint2*>(g_xh)[i] = o;
}

// ---------------- GEMM mainloop ----------------
// load one k-chunk (BK=64) for stage s: A tile [BM][BK], B tile [BN][BK],
// each row = 128 B = 8 x 16 B chunks, SW128-swizzled byte offsets.
__device__ __forceinline__ void load_stage(uint32_t sb, int s, int kt, int tid,
                                           const __half* gA, const __half* gB) {
    uint32_t a_off = sb + s * STAGE_BYTES;
    uint32_t b_off = a_off + A_STAGE_BYTES;
#pragma unroll
    for (int p = 0; p < 4; p++) {                  // 1024 16B-chunks / 256 thr
        int id = tid + p * NTHREADS;
        int row = id >> 3, ch = id & 7;
        uint32_t off = (uint32_t)row * 128 + (uint32_t)ch * 16;
        cp_async16(a_off + sw128(off),
                   gA + (size_t)row * KDIM + kt * BK + ch * 8);
    }
#pragma unroll
    for (int p = 0; p < 4; p++) {
        int id = tid + p * NTHREADS;
        int row = id >> 3, ch = id & 7;
        uint32_t off = (uint32_t)row * 128 + (uint32_t)ch * 16;
        cp_async16(b_off + sw128(off),
                   gB + (size_t)row * KDIM + kt * BK + ch * 8);
    }
    cp_commit();
}

__global__ void __launch_bounds__(NTHREADS, 2)
gemm_kernel(const float* __restrict__ bias, float* __restrict__ out) {
    extern __shared__ char smem[];
    uint32_t sb = smem_to_u32(smem);
    int tid = threadIdx.x;
    int wid = tid >> 5, lane = tid & 31;
    int warp_m = wid >> 2;            // 0..1  (64 rows each)
    int warp_n = wid & 3;             // 0..3  (32 cols each)
    int nbase = blockIdx.x * BN;
    int mbase = blockIdx.y * BM;

    const __half* gA = g_xh + (size_t)mbase * KDIM;
    const __half* gB = g_wq + (size_t)nbase * KDIM;

    float acc[4][4][4];
#pragma unroll
    for (int i = 0; i < 4; i++)
#pragma unroll
        for (int j = 0; j < 4; j++)
#pragma unroll
            for (int r = 0; r < 4; r++) acc[i][j][r] = 0.f;

    // ldmatrix per-lane base addressing (rows within tile, 16B chunk index)
    int a_row_base = warp_m * 64 + ((lane >> 3) & 1) * 8 + (lane & 7);
    int b_row_base = warp_n * 32 + ((lane >> 3) & 1) * 8 + (lane & 7);
    int ch_base = lane >> 4;          // 0..1

    // prologue: fill STAGES-1 stages
    load_stage(sb, 0, 0, tid, gA, gB);
    load_stage(sb, 1, 1, tid, gA, gB);

    int cur = 0, nxt_s = 2;
    for (int kt = 0; kt < KT; kt++) {
        cp_wait<STAGES - 2>();
        __syncthreads();

        int nxt = kt + STAGES - 1;
        if (nxt < KT) load_stage(sb, nxt_s, nxt, tid, gA, gB);
        else cp_commit();

        uint32_t a_off = sb + cur * STAGE_BYTES;
        uint32_t b_off = a_off + A_STAGE_BYTES;

#pragma unroll
        for (int kk = 0; kk < 4; kk++) {
            uint32_t afr[4][4];
#pragma unroll
            for (int i = 0; i < 4; i++) {
                uint32_t off = (uint32_t)(a_row_base + i * 16) * 128
                             + (uint32_t)(ch_base + kk * 2) * 16;
                ldsm4(afr[i], a_off + sw128(off));
            }
            uint32_t bfr[2][4];
#pragma unroll
            for (int g = 0; g < 2; g++) {
                uint32_t off = (uint32_t)(b_row_base + g * 16) * 128
                             + (uint32_t)(ch_base + kk * 2) * 16;
                ldsm4(bfr[g], b_off + sw128(off));
            }
#pragma unroll
            for (int i = 0; i < 4; i++)
#pragma unroll
                for (int j = 0; j < 4; j++)
                    mma16816(acc[i][j], afr[i],
                             bfr[j >> 1][j & 1], bfr[j >> 1][(j & 1) + 2]);
        }

        cur = (cur == STAGES - 1) ? 0 : cur + 1;
        nxt_s = (nxt_s == STAGES - 1) ? 0 : nxt_s + 1;
    }

    // epilogue: direct to gmem with bias
    int m0 = mbase + warp_m * 64 + (lane >> 2);
    int n0 = nbase + warp_n * 32 + (lane & 3) * 2;
    float2 bj[4];
#pragma unroll
    for (int j = 0; j < 4; j++)
        bj[j] = *reinterpret_cast<const float2*>(bias + n0 + j * 8);
#pragma unroll
    for (int i = 0; i < 4; i++) {
        float* row_lo = out + (size_t)(m0 + i * 16) * ODIM;
        float* row_hi = out + (size_t)(m0 + i * 16 + 8) * ODIM;
#pragma unroll
        for (int j = 0; j < 4; j++) {
            float2 lo = { acc[i][j][0] + bj[j].x, acc[i][j][1] + bj[j].y };
            float2 hi = { acc[i][j][2] + bj[j].x, acc[i][j][3] + bj[j].y };
            *reinterpret_cast<float2*>(row_lo + n0 + j * 8) = lo;
            *reinterpret_cast<float2*>(row_hi + n0 + j * 8) = hi;
        }
    }
}

// ---------------- launch ----------------
extern "C" void kernel_launch(void* const* d_in, const int* in_sizes, int n_in,
                              void* d_out, int out_size) {
    const float* x     = (const float*)d_in[0];
    const float* w     = (const float*)d_in[1];
    const float* bias  = (const float*)d_in[2];
    const float* basis = (const float*)d_in[3];
    float* out = (float*)d_out;

    cudaFuncSetAttribute(gemm_kernel, cudaFuncAttributeMaxDynamicSharedMemorySize,
                         SMEM_TOTAL);

    int nw4 = (ODIM * KDIM) / 4;
    int nx4 = (TOKENS * KDIM) / 4;
    quantize_w_kernel<<<(nw4 + 255) / 256, 256>>>(w, basis, nw4);
    convert_x_kernel<<<(nx4 + 255) / 256, 256>>>(x, nx4);
    gemm_kernel<<<dim3(ODIM / BN, TOKENS / BM), NTHREADS, SMEM_TOTAL>>>(bias, out);
}